// round 4
// baseline (speedup 1.0000x reference)
#include <cuda_runtime.h>
#include <math.h>

#define N_LIG 1024
#define N_POK 8192
#define D     256
#define ADIM  512
#define NH    4
#define HD    64

// ---------------- device scratch (no allocations allowed) ----------------
__device__ float g_Q[N_LIG * D];
__device__ float g_K[N_POK * D];
__device__ float g_V[N_POK * D];
__device__ int   g_nbr[(size_t)N_LIG * N_POK];
__device__ int   g_cnt[N_LIG];

// ---------------- tiled FP32 GEMM: C[M,N] = A[M,K] @ W[K,N] + bias ----------------
#define BM 128
#define BN 64
#define BK 16

__global__ __launch_bounds__(256) void gemm_bias_kernel(
    const float* __restrict__ A, const float* __restrict__ W,
    const float* __restrict__ bias, float* __restrict__ C,
    int M, int N, int K)
{
    __shared__ float As[BK][BM + 4];
    __shared__ float Bs[BK][BN];

    const int tid = threadIdx.x;
    const int bm = blockIdx.y * BM;
    const int bn = blockIdx.x * BN;
    const int tx = tid & 15;        // 0..15 -> 4 output cols each
    const int ty = tid >> 4;        // 0..15 -> 8 output rows each

    float acc[8][4];
#pragma unroll
    for (int m = 0; m < 8; m++)
#pragma unroll
        for (int n = 0; n < 4; n++) acc[m][n] = 0.f;

    for (int k0 = 0; k0 < K; k0 += BK) {
        // load A tile (BM x BK) -> As transposed, via float4
#pragma unroll
        for (int ld = 0; ld < 2; ld++) {
            int f = tid * 2 + ld;            // 0..511 float4s
            int row = f >> 2;                // 0..127
            int c4 = (f & 3) * 4;            // 0,4,8,12
            float4 v = *(const float4*)(A + (size_t)(bm + row) * K + k0 + c4);
            As[c4 + 0][row] = v.x;
            As[c4 + 1][row] = v.y;
            As[c4 + 2][row] = v.z;
            As[c4 + 3][row] = v.w;
        }
        // load W tile (BK x BN)
        {
            int r = tid >> 4;                // 0..15
            int c4 = (tid & 15) * 4;         // 0..60
            *(float4*)(&Bs[r][c4]) = *(const float4*)(W + (size_t)(k0 + r) * N + bn + c4);
        }
        __syncthreads();

#pragma unroll
        for (int kk = 0; kk < BK; kk++) {
            float a[8], b[4];
            *(float4*)(a)     = *(const float4*)(&As[kk][ty * 8]);
            *(float4*)(a + 4) = *(const float4*)(&As[kk][ty * 8 + 4]);
            *(float4*)(b)     = *(const float4*)(&Bs[kk][tx * 4]);
#pragma unroll
            for (int m = 0; m < 8; m++)
#pragma unroll
                for (int n = 0; n < 4; n++)
                    acc[m][n] = fmaf(a[m], b[n], acc[m][n]);
        }
        __syncthreads();
    }

    float4 bv = *(const float4*)(bias + bn + tx * 4);
#pragma unroll
    for (int m = 0; m < 8; m++) {
        int row = bm + ty * 8 + m;
        float4 ov;
        ov.x = acc[m][0] + bv.x;
        ov.y = acc[m][1] + bv.y;
        ov.z = acc[m][2] + bv.z;
        ov.w = acc[m][3] + bv.w;
        *(float4*)(C + (size_t)row * N + bn + tx * 4) = ov;
    }
}

// ---------------- deterministic neighbor compaction: 1 warp per ligand ----------------
__global__ __launch_bounds__(256) void compact_kernel(
    const float* __restrict__ x_lig, const float* __restrict__ x_pok)
{
    const int wg = (blockIdx.x * blockDim.x + threadIdx.x) >> 5;
    const int lane = threadIdx.x & 31;
    if (wg >= N_LIG) return;

    const float xi0 = x_lig[wg * 3 + 0];
    const float xi1 = x_lig[wg * 3 + 1];
    const float xi2 = x_lig[wg * 3 + 2];
    int* row = g_nbr + (size_t)wg * N_POK;
    int base = 0;

    for (int c = 0; c < N_POK; c += 32) {
        int j = c + lane;
        float r0 = x_pok[j * 3 + 0] - xi0;
        float r1 = x_pok[j * 3 + 1] - xi1;
        float r2 = x_pok[j * 3 + 2] - xi2;
        float d = sqrtf(r0 * r0 + r1 * r1 + r2 * r2);
        bool m = d < 10.0f;   // match reference: norm < EDGE_CUTOFF
        unsigned bal = __ballot_sync(0xffffffffu, m);
        if (m) row[base + __popc(bal & ((1u << lane) - 1u))] = j;
        base += __popc(bal);
    }
    if (lane == 0) g_cnt[wg] = base;
}

// ---------------- fused attention + epilogue: 1 block (256 thr) per ligand ----------------
__global__ __launch_bounds__(256) void attn_kernel(
    const float* __restrict__ h_lig, const float* __restrict__ x_lig,
    const float* __restrict__ x_pok,
    const float* __restrict__ e1w, const float* __restrict__ e1b,
    const float* __restrict__ e2w, const float* __restrict__ e2b,
    const float* __restrict__ ow,  const float* __restrict__ ob,
    const float* __restrict__ c1w, const float* __restrict__ c1b,
    const float* __restrict__ c2w, const float* __restrict__ c2b,
    float* __restrict__ out)
{
    const int i    = blockIdx.x;
    const int tid  = threadIdx.x;      // 256
    const int lane = tid & 31;
    const int wrp  = tid >> 5;         // 8 warps
    const int hh   = tid >> 6;         // head of this output element

    __shared__ float sQ[D];
    __shared__ float sE1w[D], sE1b[D], sE2w[D * 4];
    __shared__ float sS[32 * 4];       // tile scores [j][h]
    __shared__ float sP[32 * 4];       // tile probs  [j][h]
    __shared__ float sU[32 * 3];       // unit rel-pos
    __shared__ int   sJ[32];
    __shared__ float sM[4], sL[4], sAl[4];
    __shared__ float sC[12];           // coord numerators [h][dim]
    __shared__ float sHa[D];
    __shared__ float sRed[8];

    sQ[tid]   = g_Q[(size_t)i * D + tid];
    sE1w[tid] = e1w[tid];
    sE1b[tid] = e1b[tid];
#pragma unroll
    for (int r = 0; r < 4; r++) sE2w[tid + r * 256] = e2w[tid + r * 256];
    if (tid < 4)  { sM[tid] = -INFINITY; sL[tid] = 0.f; }
    if (tid < 12) sC[tid] = 0.f;

    const float xi0 = x_lig[i * 3 + 0];
    const float xi1 = x_lig[i * 3 + 1];
    const float xi2 = x_lig[i * 3 + 2];
    const float eb0 = e2b[0], eb1 = e2b[1], eb2 = e2b[2], eb3 = e2b[3];

    float o = 0.f;   // this thread's output element (dim tid)
    const int cnt = g_cnt[i];
    __syncthreads();

    // per-lane Q registers, two 32-chunks per head
    const float q00 = sQ[lane],       q01 = sQ[lane + 32];
    const float q10 = sQ[64 + lane],  q11 = sQ[96 + lane];
    const float q20 = sQ[128 + lane], q21 = sQ[160 + lane];
    const float q30 = sQ[192 + lane], q31 = sQ[224 + lane];

    for (int t0 = 0; t0 < cnt; t0 += 32) {
        const int tn = min(32, cnt - t0);
        if (tid < tn) sJ[tid] = g_nbr[(size_t)i * N_POK + t0 + tid];
        __syncthreads();

        // ---- phase A: 8 warps, warp w handles jj = w, w+8, w+16, w+24 ----
        for (int jj = wrp; jj < tn; jj += 8) {
            const int jn = sJ[jj];
            float r0 = x_pok[jn * 3 + 0] - xi0;
            float r1 = x_pok[jn * 3 + 1] - xi1;
            float r2 = x_pok[jn * 3 + 2] - xi2;
            float d  = sqrtf(r0 * r0 + r1 * r1 + r2 * r2);

            // edge MLP: silu(d*e1w+e1b) @ e2w  (lane covers 8 of 256 hidden)
            float a0 = 0.f, a1 = 0.f, a2 = 0.f, a3 = 0.f;
#pragma unroll
            for (int r = 0; r < 8; r++) {
                int k = lane + 32 * r;
                float t  = fmaf(d, sE1w[k], sE1b[k]);
                float sv = __fdividef(t, 1.f + __expf(-t));
                float4 w4 = *(const float4*)(&sE2w[k * 4]);
                a0 = fmaf(sv, w4.x, a0);
                a1 = fmaf(sv, w4.y, a1);
                a2 = fmaf(sv, w4.z, a2);
                a3 = fmaf(sv, w4.w, a3);
            }

            // QK dots per head (coalesced 128B reads of K row)
            const float* Kr = g_K + (size_t)jn * D;
            float s0 = q00 * Kr[lane]       + q01 * Kr[lane + 32];
            float s1 = q10 * Kr[64 + lane]  + q11 * Kr[96 + lane];
            float s2 = q20 * Kr[128 + lane] + q21 * Kr[160 + lane];
            float s3 = q30 * Kr[192 + lane] + q31 * Kr[224 + lane];

            // fold QK partial (scaled) into edge-MLP partial BEFORE reduction:
            // sum(s)*0.125 + sum(a) == sum(s*0.125 + a)  -> 4 reductions, not 8
            float c0 = fmaf(s0, 0.125f, a0);
            float c1 = fmaf(s1, 0.125f, a1);
            float c2 = fmaf(s2, 0.125f, a2);
            float c3 = fmaf(s3, 0.125f, a3);

#pragma unroll
            for (int off = 16; off; off >>= 1) {
                c0 += __shfl_xor_sync(0xffffffffu, c0, off);
                c1 += __shfl_xor_sync(0xffffffffu, c1, off);
                c2 += __shfl_xor_sync(0xffffffffu, c2, off);
                c3 += __shfl_xor_sync(0xffffffffu, c3, off);
            }
            if (lane == 0) {
                sS[jj * 4 + 0] = c0 + eb0;
                sS[jj * 4 + 1] = c1 + eb1;
                sS[jj * 4 + 2] = c2 + eb2;
                sS[jj * 4 + 3] = c3 + eb3;
                float inv = __fdividef(1.f, d + 1e-8f);
                sU[jj * 3 + 0] = r0 * inv;
                sU[jj * 3 + 1] = r1 * inv;
                sU[jj * 3 + 2] = r2 * inv;
            }
        }
        __syncthreads();

        // ---- phase B: online softmax bookkeeping, one warp per head ----
        if (wrp < 4) {
            const int h2 = wrp;
            float v = (lane < tn) ? sS[lane * 4 + h2] : -INFINITY;
            float mx = v;
#pragma unroll
            for (int off = 16; off; off >>= 1)
                mx = fmaxf(mx, __shfl_xor_sync(0xffffffffu, mx, off));
            float mold = sM[h2];
            float mnew = fmaxf(mold, mx);
            float p = (lane < tn) ? __expf(v - mnew) : 0.f;
            sP[lane * 4 + h2] = p;
            float sum = p;
#pragma unroll
            for (int off = 16; off; off >>= 1)
                sum += __shfl_xor_sync(0xffffffffu, sum, off);
            if (lane == 0) {
                float al = __expf(mold - mnew);   // 0 on first tile
                sAl[h2] = al;
                sL[h2]  = sL[h2] * al + sum;
                sM[h2]  = mnew;
            }
        }
        __syncthreads();

        // ---- phase C: accumulate V (all 256 threads) + coord numerators ----
        {
            float al = sAl[hh];
            o *= al;
            int jj = 0;
            for (; jj + 4 <= tn; jj += 4) {
                int j0 = sJ[jj], j1 = sJ[jj + 1], j2 = sJ[jj + 2], j3 = sJ[jj + 3];
                float p0 = sP[(jj + 0) * 4 + hh];
                float p1 = sP[(jj + 1) * 4 + hh];
                float p2 = sP[(jj + 2) * 4 + hh];
                float p3 = sP[(jj + 3) * 4 + hh];
                float v0 = g_V[(size_t)j0 * D + tid];
                float v1 = g_V[(size_t)j1 * D + tid];
                float v2 = g_V[(size_t)j2 * D + tid];
                float v3 = g_V[(size_t)j3 * D + tid];
                o = fmaf(p0, v0, o);
                o = fmaf(p1, v1, o);
                o = fmaf(p2, v2, o);
                o = fmaf(p3, v3, o);
            }
            for (; jj < tn; jj++)
                o = fmaf(sP[jj * 4 + hh], g_V[(size_t)sJ[jj] * D + tid], o);
        }
        if (tid < 12) {
            int h2 = tid / 3, dd = tid - h2 * 3;
            float c = sC[tid] * sAl[h2];
            for (int jj = 0; jj < tn; jj++)
                c = fmaf(sP[jj * 4 + h2], sU[jj * 3 + dd], c);
            sC[tid] = c;
        }
        __syncthreads();
    }

    // ---- finalize: normalize, epilogue matvecs, coord update ----
    float l  = sL[hh];
    float ha = (l > 0.f) ? o * __fdividef(1.f, l) : 0.f;   // nan_to_num for empty rows
    sHa[tid] = ha;
    __syncthreads();

    // h_out = h_lig + h_attended @ ow + ob
    float acc = ob[tid];
#pragma unroll 8
    for (int k = 0; k < D; k++)
        acc = fmaf(sHa[k], ow[(size_t)k * D + tid], acc);
    out[(size_t)i * D + tid] = h_lig[(size_t)i * D + tid] + acc;

    // coord_scale = silu(h_attended @ c1w + c1b) @ c2w + c2b
    float acc2 = c1b[tid];
#pragma unroll 8
    for (int k = 0; k < D; k++)
        acc2 = fmaf(sHa[k], c1w[(size_t)k * D + tid], acc2);
    float z = __fdividef(acc2, 1.f + __expf(-acc2)) * c2w[tid];
#pragma unroll
    for (int off = 16; off; off >>= 1)
        z += __shfl_xor_sync(0xffffffffu, z, off);
    if (lane == 0) sRed[wrp] = z;
    __syncthreads();

    if (tid == 0) {
        float sc = c2b[0];
#pragma unroll
        for (int r = 0; r < 8; r++) sc += sRed[r];
        float* ox = out + (size_t)N_LIG * D;
#pragma unroll
        for (int dd = 0; dd < 3; dd++) {
            float cm = 0.f;
#pragma unroll
            for (int h2 = 0; h2 < 4; h2++) {
                float lh = sL[h2];
                if (lh > 0.f) cm += __fdividef(sC[h2 * 3 + dd], lh);
            }
            cm *= 0.25f;   // mean over heads
            ox[i * 3 + dd] = x_lig[i * 3 + dd] + sc * cm;
        }
    }
}

// ---------------- launch ----------------
extern "C" void kernel_launch(void* const* d_in, const int* in_sizes, int n_in,
                              void* d_out, int out_size)
{
    const float* h_lig = (const float*)d_in[0];
    const float* x_lig = (const float*)d_in[1];
    const float* h_ato = (const float*)d_in[2];
    const float* x_pok = (const float*)d_in[3];
    const float* qw  = (const float*)d_in[4];
    const float* qb  = (const float*)d_in[5];
    const float* kw  = (const float*)d_in[6];
    const float* kb  = (const float*)d_in[7];
    const float* vw  = (const float*)d_in[8];
    const float* vb  = (const float*)d_in[9];
    const float* ow  = (const float*)d_in[10];
    const float* ob  = (const float*)d_in[11];
    const float* e1w = (const float*)d_in[12];
    const float* e1b = (const float*)d_in[13];
    const float* e2w = (const float*)d_in[14];
    const float* e2b = (const float*)d_in[15];
    const float* c1w = (const float*)d_in[16];
    const float* c1b = (const float*)d_in[17];
    const float* c2w = (const float*)d_in[18];
    const float* c2b = (const float*)d_in[19];
    float* out = (float*)d_out;

    void *pQ, *pK, *pV;
    cudaGetSymbolAddress(&pQ, g_Q);
    cudaGetSymbolAddress(&pK, g_K);
    cudaGetSymbolAddress(&pV, g_V);

    // projections
    gemm_bias_kernel<<<dim3(D / BN, N_LIG / BM), 256>>>(h_lig, qw, qb, (float*)pQ, N_LIG, D, D);
    gemm_bias_kernel<<<dim3(D / BN, N_POK / BM), 256>>>(h_ato, kw, kb, (float*)pK, N_POK, D, ADIM);
    gemm_bias_kernel<<<dim3(D / BN, N_POK / BM), 256>>>(h_ato, vw, vb, (float*)pV, N_POK, D, ADIM);

    // neighbor compaction (deterministic, ordered)
    compact_kernel<<<N_LIG / 8, 256>>>(x_lig, x_pok);

    // fused attention + epilogue
    attn_kernel<<<N_LIG, 256>>>(h_lig, x_lig, x_pok,
                                e1w, e1b, e2w, e2b,
                                ow, ob, c1w, c1b, c2w, c2b, out);
}

// round 6
// speedup vs baseline: 1.0006x; 1.0006x over previous
#include <cuda_runtime.h>
#include <math.h>

#define N_LIG 1024
#define N_POK 8192
#define D     256
#define ADIM  512
#define NH    4
#define HD    64

// ---------------- device scratch (no allocations allowed) ----------------
__device__ float  g_Q[N_LIG * D];
__device__ float  g_K[N_POK * D];
__device__ float  g_V[N_POK * D];
__device__ int    g_nbr[(size_t)N_LIG * N_POK];
__device__ float4 g_geo[(size_t)N_LIG * N_POK];   // (ux, uy, uz, d) per compacted pair
__device__ int    g_cnt[N_LIG];

// ---------------- tiled FP32 GEMM: C[M,N] = A[M,K] @ W[K,N] + bias ----------------
#define BM 128
#define BN 64
#define BK 16

__global__ __launch_bounds__(256) void gemm_bias_kernel(
    const float* __restrict__ A, const float* __restrict__ W,
    const float* __restrict__ bias, float* __restrict__ C,
    int M, int N, int K)
{
    __shared__ float As[BK][BM + 4];
    __shared__ float Bs[BK][BN];

    const int tid = threadIdx.x;
    const int bm = blockIdx.y * BM;
    const int bn = blockIdx.x * BN;
    const int tx = tid & 15;        // 0..15 -> 4 output cols each
    const int ty = tid >> 4;        // 0..15 -> 8 output rows each

    float acc[8][4];
#pragma unroll
    for (int m = 0; m < 8; m++)
#pragma unroll
        for (int n = 0; n < 4; n++) acc[m][n] = 0.f;

    for (int k0 = 0; k0 < K; k0 += BK) {
        // load A tile (BM x BK) -> As transposed, via float4
#pragma unroll
        for (int ld = 0; ld < 2; ld++) {
            int f = tid * 2 + ld;            // 0..511 float4s
            int row = f >> 2;                // 0..127
            int c4 = (f & 3) * 4;            // 0,4,8,12
            float4 v = *(const float4*)(A + (size_t)(bm + row) * K + k0 + c4);
            As[c4 + 0][row] = v.x;
            As[c4 + 1][row] = v.y;
            As[c4 + 2][row] = v.z;
            As[c4 + 3][row] = v.w;
        }
        // load W tile (BK x BN)
        {
            int r = tid >> 4;                // 0..15
            int c4 = (tid & 15) * 4;         // 0..60
            *(float4*)(&Bs[r][c4]) = *(const float4*)(W + (size_t)(k0 + r) * N + bn + c4);
        }
        __syncthreads();

#pragma unroll
        for (int kk = 0; kk < BK; kk++) {
            float a[8], b[4];
            *(float4*)(a)     = *(const float4*)(&As[kk][ty * 8]);
            *(float4*)(a + 4) = *(const float4*)(&As[kk][ty * 8 + 4]);
            *(float4*)(b)     = *(const float4*)(&Bs[kk][tx * 4]);
#pragma unroll
            for (int m = 0; m < 8; m++)
#pragma unroll
                for (int n = 0; n < 4; n++)
                    acc[m][n] = fmaf(a[m], b[n], acc[m][n]);
        }
        __syncthreads();
    }

    float4 bv = *(const float4*)(bias + bn + tx * 4);
#pragma unroll
    for (int m = 0; m < 8; m++) {
        int row = bm + ty * 8 + m;
        float4 ov;
        ov.x = acc[m][0] + bv.x;
        ov.y = acc[m][1] + bv.y;
        ov.z = acc[m][2] + bv.z;
        ov.w = acc[m][3] + bv.w;
        *(float4*)(C + (size_t)row * N + bn + tx * 4) = ov;
    }
}

// ---------------- neighbor compaction: 1 block (8 warps) per ligand, 2-pass ----------------
// Warp w scans pockets [w*1024, (w+1)*1024). Pass 1 counts; a scan assigns per-warp
// offsets; pass 2 rewrites mask and stores compacted index + (unit rel pos, distance).
__global__ __launch_bounds__(256) void compact_kernel(
    const float* __restrict__ x_lig, const float* __restrict__ x_pok)
{
    const int i    = blockIdx.x;
    const int tid  = threadIdx.x;
    const int lane = tid & 31;
    const int w    = tid >> 5;          // 8 warps
    const int SPAN = N_POK / 8;         // 1024 pockets per warp

    __shared__ int sCnt[8], sOff[8];

    const float xi0 = x_lig[i * 3 + 0];
    const float xi1 = x_lig[i * 3 + 1];
    const float xi2 = x_lig[i * 3 + 2];
    const int j0 = w * SPAN;

    // pass 1: count
    int cnt = 0;
    for (int c = 0; c < SPAN; c += 32) {
        int j = j0 + c + lane;
        float r0 = x_pok[j * 3 + 0] - xi0;
        float r1 = x_pok[j * 3 + 1] - xi1;
        float r2 = x_pok[j * 3 + 2] - xi2;
        float d = sqrtf(r0 * r0 + r1 * r1 + r2 * r2);
        cnt += __popc(__ballot_sync(0xffffffffu, d < 10.0f));
    }
    if (lane == 0) sCnt[w] = cnt;
    __syncthreads();
    if (tid == 0) {
        int a = 0;
#pragma unroll
        for (int k = 0; k < 8; k++) { sOff[k] = a; a += sCnt[k]; }
        g_cnt[i] = a;
    }
    __syncthreads();

    // pass 2: write compacted indices + geometry (x_pok hits L1 now)
    int base = sOff[w];
    int*    row = g_nbr + (size_t)i * N_POK;
    float4* geo = g_geo + (size_t)i * N_POK;
    for (int c = 0; c < SPAN; c += 32) {
        int j = j0 + c + lane;
        float r0 = x_pok[j * 3 + 0] - xi0;
        float r1 = x_pok[j * 3 + 1] - xi1;
        float r2 = x_pok[j * 3 + 2] - xi2;
        float d = sqrtf(r0 * r0 + r1 * r1 + r2 * r2);
        bool m = d < 10.0f;
        unsigned bal = __ballot_sync(0xffffffffu, m);
        if (m) {
            int p = base + __popc(bal & ((1u << lane) - 1u));
            row[p] = j;
            float inv = __fdividef(1.f, d + 1e-8f);
            geo[p] = make_float4(r0 * inv, r1 * inv, r2 * inv, d);
        }
        base += __popc(bal);
    }
}

// ---------------- fused attention + epilogue: 1 block (256 thr) per ligand ----------------
__global__ __launch_bounds__(256) void attn_kernel(
    const float* __restrict__ h_lig, const float* __restrict__ x_lig,
    const float* __restrict__ e1w, const float* __restrict__ e1b,
    const float* __restrict__ e2w, const float* __restrict__ e2b,
    const float* __restrict__ ow,  const float* __restrict__ ob,
    const float* __restrict__ c1w, const float* __restrict__ c1b,
    const float* __restrict__ c2w, const float* __restrict__ c2b,
    float* __restrict__ out)
{
    const int i    = blockIdx.x;
    const int tid  = threadIdx.x;      // 256
    const int lane = tid & 31;
    const int wrp  = tid >> 5;         // 8 warps
    const int hh   = tid >> 6;         // head of this output element

    __shared__ float sQ[D];
    __shared__ float sE1w[D], sE1b[D], sE2w[D * 4];
    __shared__ float sS[32 * 4];       // tile scores [j][h]
    __shared__ float sP[32 * 4];       // tile probs  [j][h]
    __shared__ float sU[32 * 3];       // unit rel-pos
    __shared__ int   sJ[32];
    __shared__ float sM[4], sL[4], sAl[4];
    __shared__ float sC[12];           // coord numerators [h][dim]
    __shared__ float sHa[D];
    __shared__ float sRed[8];

    sQ[tid]   = g_Q[(size_t)i * D + tid];
    sE1w[tid] = e1w[tid];
    sE1b[tid] = e1b[tid];
#pragma unroll
    for (int r = 0; r < 4; r++) sE2w[tid + r * 256] = e2w[tid + r * 256];
    if (tid < 4)  { sM[tid] = -INFINITY; sL[tid] = 0.f; }
    if (tid < 12) sC[tid] = 0.f;

    const float eb0 = e2b[0], eb1 = e2b[1], eb2 = e2b[2], eb3 = e2b[3];

    float o = 0.f;   // this thread's output element (dim tid)
    const int cnt = g_cnt[i];
    __syncthreads();

    // per-lane Q registers, two 32-chunks per head
    const float q00 = sQ[lane],       q01 = sQ[lane + 32];
    const float q10 = sQ[64 + lane],  q11 = sQ[96 + lane];
    const float q20 = sQ[128 + lane], q21 = sQ[160 + lane];
    const float q30 = sQ[192 + lane], q31 = sQ[224 + lane];

    for (int t0 = 0; t0 < cnt; t0 += 32) {
        const int tn = min(32, cnt - t0);
        if (tid < tn) sJ[tid] = g_nbr[(size_t)i * N_POK + t0 + tid];
        __syncthreads();

        // ---- phase A: 8 warps, warp w handles jj = w, w+8, w+16, w+24 ----
        for (int jj = wrp; jj < tn; jj += 8) {
            const int jn = sJ[jj];
            const float4 g = g_geo[(size_t)i * N_POK + t0 + jj];  // broadcast load
            const float d = g.w;

            // edge MLP: silu(d*e1w+e1b) @ e2w  (lane covers 8 of 256 hidden)
            float a0 = 0.f, a1 = 0.f, a2 = 0.f, a3 = 0.f;
#pragma unroll
            for (int r = 0; r < 8; r++) {
                int k = lane + 32 * r;
                float t  = fmaf(d, sE1w[k], sE1b[k]);
                float sv = __fdividef(t, 1.f + __expf(-t));
                float4 w4 = *(const float4*)(&sE2w[k * 4]);
                a0 = fmaf(sv, w4.x, a0);
                a1 = fmaf(sv, w4.y, a1);
                a2 = fmaf(sv, w4.z, a2);
                a3 = fmaf(sv, w4.w, a3);
            }

            // QK dots per head (coalesced 128B reads of K row)
            const float* Kr = g_K + (size_t)jn * D;
            float s0 = q00 * Kr[lane]       + q01 * Kr[lane + 32];
            float s1 = q10 * Kr[64 + lane]  + q11 * Kr[96 + lane];
            float s2 = q20 * Kr[128 + lane] + q21 * Kr[160 + lane];
            float s3 = q30 * Kr[192 + lane] + q31 * Kr[224 + lane];

            // fold QK partial (scaled) into edge-MLP partial BEFORE reduction:
            // sum(s)*0.125 + sum(a) == sum(s*0.125 + a)  -> 4 reductions, not 8
            float c0 = fmaf(s0, 0.125f, a0);
            float c1 = fmaf(s1, 0.125f, a1);
            float c2 = fmaf(s2, 0.125f, a2);
            float c3 = fmaf(s3, 0.125f, a3);

#pragma unroll
            for (int off = 16; off; off >>= 1) {
                c0 += __shfl_xor_sync(0xffffffffu, c0, off);
                c1 += __shfl_xor_sync(0xffffffffu, c1, off);
                c2 += __shfl_xor_sync(0xffffffffu, c2, off);
                c3 += __shfl_xor_sync(0xffffffffu, c3, off);
            }
            if (lane == 0) {
                sS[jj * 4 + 0] = c0 + eb0;
                sS[jj * 4 + 1] = c1 + eb1;
                sS[jj * 4 + 2] = c2 + eb2;
                sS[jj * 4 + 3] = c3 + eb3;
                sU[jj * 3 + 0] = g.x;
                sU[jj * 3 + 1] = g.y;
                sU[jj * 3 + 2] = g.z;
            }
        }
        __syncthreads();

        // ---- phase B: online softmax bookkeeping, one warp per head ----
        if (wrp < 4) {
            const int h2 = wrp;
            float v = (lane < tn) ? sS[lane * 4 + h2] : -INFINITY;
            float mx = v;
#pragma unroll
            for (int off = 16; off; off >>= 1)
                mx = fmaxf(mx, __shfl_xor_sync(0xffffffffu, mx, off));
            float mold = sM[h2];
            float mnew = fmaxf(mold, mx);
            float p = (lane < tn) ? __expf(v - mnew) : 0.f;
            sP[lane * 4 + h2] = p;
            float sum = p;
#pragma unroll
            for (int off = 16; off; off >>= 1)
                sum += __shfl_xor_sync(0xffffffffu, sum, off);
            if (lane == 0) {
                float al = __expf(mold - mnew);   // 0 on first tile
                sAl[h2] = al;
                sL[h2]  = sL[h2] * al + sum;
                sM[h2]  = mnew;
            }
        }
        __syncthreads();

        // ---- phase C: accumulate V (all 256 threads) + coord numerators ----
        {
            float al = sAl[hh];
            o *= al;
            int jj = 0;
            for (; jj + 4 <= tn; jj += 4) {
                int j0 = sJ[jj], j1 = sJ[jj + 1], j2 = sJ[jj + 2], j3 = sJ[jj + 3];
                float p0 = sP[(jj + 0) * 4 + hh];
                float p1 = sP[(jj + 1) * 4 + hh];
                float p2 = sP[(jj + 2) * 4 + hh];
                float p3 = sP[(jj + 3) * 4 + hh];
                float v0 = g_V[(size_t)j0 * D + tid];
                float v1 = g_V[(size_t)j1 * D + tid];
                float v2 = g_V[(size_t)j2 * D + tid];
                float v3 = g_V[(size_t)j3 * D + tid];
                o = fmaf(p0, v0, o);
                o = fmaf(p1, v1, o);
                o = fmaf(p2, v2, o);
                o = fmaf(p3, v3, o);
            }
            for (; jj < tn; jj++)
                o = fmaf(sP[jj * 4 + hh], g_V[(size_t)sJ[jj] * D + tid], o);
        }
        if (tid < 12) {
            int h2 = tid / 3, dd = tid - h2 * 3;
            float c = sC[tid] * sAl[h2];
            for (int jj = 0; jj < tn; jj++)
                c = fmaf(sP[jj * 4 + h2], sU[jj * 3 + dd], c);
            sC[tid] = c;
        }
        __syncthreads();
    }

    // ---- finalize: normalize, epilogue matvecs, coord update ----
    float l  = sL[hh];
    float ha = (l > 0.f) ? o * __fdividef(1.f, l) : 0.f;   // nan_to_num for empty rows
    sHa[tid] = ha;
    __syncthreads();

    // h_out = h_lig + h_attended @ ow + ob
    float acc = ob[tid];
#pragma unroll 8
    for (int k = 0; k < D; k++)
        acc = fmaf(sHa[k], ow[(size_t)k * D + tid], acc);
    out[(size_t)i * D + tid] = h_lig[(size_t)i * D + tid] + acc;

    // coord_scale = silu(h_attended @ c1w + c1b) @ c2w + c2b
    float acc2 = c1b[tid];
#pragma unroll 8
    for (int k = 0; k < D; k++)
        acc2 = fmaf(sHa[k], c1w[(size_t)k * D + tid], acc2);
    float z = __fdividef(acc2, 1.f + __expf(-acc2)) * c2w[tid];
#pragma unroll
    for (int off = 16; off; off >>= 1)
        z += __shfl_xor_sync(0xffffffffu, z, off);
    if (lane == 0) sRed[wrp] = z;
    __syncthreads();

    if (tid == 0) {
        float sc = c2b[0];
#pragma unroll
        for (int r = 0; r < 8; r++) sc += sRed[r];
        float* ox = out + (size_t)N_LIG * D;
#pragma unroll
        for (int dd = 0; dd < 3; dd++) {
            float cm = 0.f;
#pragma unroll
            for (int h2 = 0; h2 < 4; h2++) {
                float lh = sL[h2];
                if (lh > 0.f) cm += __fdividef(sC[h2 * 3 + dd], lh);
            }
            cm *= 0.25f;   // mean over heads
            ox[i * 3 + dd] = x_lig[i * 3 + dd] + sc * cm;
        }
    }
}

// ---------------- launch ----------------
extern "C" void kernel_launch(void* const* d_in, const int* in_sizes, int n_in,
                              void* d_out, int out_size)
{
    const float* h_lig = (const float*)d_in[0];
    const float* x_lig = (const float*)d_in[1];
    const float* h_ato = (const float*)d_in[2];
    const float* x_pok = (const float*)d_in[3];
    const float* qw  = (const float*)d_in[4];
    const float* qb  = (const float*)d_in[5];
    const float* kw  = (const float*)d_in[6];
    const float* kb  = (const float*)d_in[7];
    const float* vw  = (const float*)d_in[8];
    const float* vb  = (const float*)d_in[9];
    const float* ow  = (const float*)d_in[10];
    const float* ob  = (const float*)d_in[11];
    const float* e1w = (const float*)d_in[12];
    const float* e1b = (const float*)d_in[13];
    const float* e2w = (const float*)d_in[14];
    const float* e2b = (const float*)d_in[15];
    const float* c1w = (const float*)d_in[16];
    const float* c1b = (const float*)d_in[17];
    const float* c2w = (const float*)d_in[18];
    const float* c2b = (const float*)d_in[19];
    float* out = (float*)d_out;

    void *pQ, *pK, *pV;
    cudaGetSymbolAddress(&pQ, g_Q);
    cudaGetSymbolAddress(&pK, g_K);
    cudaGetSymbolAddress(&pV, g_V);

    // neighbor compaction first (independent of projections)
    compact_kernel<<<N_LIG, 256>>>(x_lig, x_pok);

    // projections
    gemm_bias_kernel<<<dim3(D / BN, N_LIG / BM), 256>>>(h_lig, qw, qb, (float*)pQ, N_LIG, D, D);
    gemm_bias_kernel<<<dim3(D / BN, N_POK / BM), 256>>>(h_ato, kw, kb, (float*)pK, N_POK, D, ADIM);
    gemm_bias_kernel<<<dim3(D / BN, N_POK / BM), 256>>>(h_ato, vw, vb, (float*)pV, N_POK, D, ADIM);

    // fused attention + epilogue
    attn_kernel<<<N_LIG, 256>>>(h_lig, x_lig,
                                e1w, e1b, e2w, e2b,
                                ow, ob, c1w, c1b, c2w, c2b, out);
}

// round 12
// speedup vs baseline: 1.4320x; 1.4311x over previous
#include <cuda_runtime.h>
#include <math.h>

#define N_LIG 1024
#define N_POK 8192
#define D     256
#define ADIM  512
#define NH    4
#define HD    64

#define NTAB      8192
#define TAB_SCALE (NTAB / 10.0f)     // d in [0,10) -> index
#define TAB_INV   (10.0f / NTAB)

// ---------------- device scratch (no allocations allowed) ----------------
__device__ float  g_Q[N_LIG * D];
__device__ float  g_K[N_POK * D];
__device__ float  g_V[N_POK * D];
__device__ int    g_nbr[(size_t)N_LIG * N_POK];
__device__ float4 g_geo[(size_t)N_LIG * N_POK];   // (ux, uy, uz, d) per compacted pair
__device__ int    g_cnt[N_LIG];
__device__ float4 g_tab[NTAB + 1];                // edge_attr(d) + e2b, per head

// ---------------- edge-MLP lookup table: one warp per entry ----------------
__global__ __launch_bounds__(256) void edge_tab_kernel(
    const float* __restrict__ e1w, const float* __restrict__ e1b,
    const float* __restrict__ e2w, const float* __restrict__ e2b)
{
    const int entry = blockIdx.x * 8 + (threadIdx.x >> 5);
    const int lane  = threadIdx.x & 31;
    if (entry > NTAB) return;
    const float d = entry * TAB_INV;

    float a0 = 0.f, a1 = 0.f, a2 = 0.f, a3 = 0.f;
#pragma unroll
    for (int r = 0; r < 8; r++) {
        int k = lane + 32 * r;
        float t  = fmaf(d, e1w[k], e1b[k]);
        float sv = __fdividef(t, 1.f + __expf(-t));
        float4 w4 = *(const float4*)(&e2w[k * 4]);
        a0 = fmaf(sv, w4.x, a0);
        a1 = fmaf(sv, w4.y, a1);
        a2 = fmaf(sv, w4.z, a2);
        a3 = fmaf(sv, w4.w, a3);
    }
#pragma unroll
    for (int off = 16; off; off >>= 1) {
        a0 += __shfl_xor_sync(0xffffffffu, a0, off);
        a1 += __shfl_xor_sync(0xffffffffu, a1, off);
        a2 += __shfl_xor_sync(0xffffffffu, a2, off);
        a3 += __shfl_xor_sync(0xffffffffu, a3, off);
    }
    if (lane == 0)
        g_tab[entry] = make_float4(a0 + e2b[0], a1 + e2b[1], a2 + e2b[2], a3 + e2b[3]);
}

// ---------------- tiled FP32 GEMM: C[M,N] = A[M,K] @ W[K,N] + bias ----------------
#define BM 128
#define BN 64
#define BK 16

__global__ __launch_bounds__(256) void gemm_bias_kernel(
    const float* __restrict__ A, const float* __restrict__ W,
    const float* __restrict__ bias, float* __restrict__ C,
    int M, int N, int K)
{
    __shared__ float As[BK][BM + 4];
    __shared__ float Bs[BK][BN];

    const int tid = threadIdx.x;
    const int bm = blockIdx.y * BM;
    const int bn = blockIdx.x * BN;
    const int tx = tid & 15;        // 0..15 -> 4 output cols each
    const int ty = tid >> 4;        // 0..15 -> 8 output rows each

    float acc[8][4];
#pragma unroll
    for (int m = 0; m < 8; m++)
#pragma unroll
        for (int n = 0; n < 4; n++) acc[m][n] = 0.f;

    for (int k0 = 0; k0 < K; k0 += BK) {
#pragma unroll
        for (int ld = 0; ld < 2; ld++) {
            int f = tid * 2 + ld;
            int row = f >> 2;
            int c4 = (f & 3) * 4;
            float4 v = *(const float4*)(A + (size_t)(bm + row) * K + k0 + c4);
            As[c4 + 0][row] = v.x;
            As[c4 + 1][row] = v.y;
            As[c4 + 2][row] = v.z;
            As[c4 + 3][row] = v.w;
        }
        {
            int r = tid >> 4;
            int c4 = (tid & 15) * 4;
            *(float4*)(&Bs[r][c4]) = *(const float4*)(W + (size_t)(k0 + r) * N + bn + c4);
        }
        __syncthreads();

#pragma unroll
        for (int kk = 0; kk < BK; kk++) {
            float a[8], b[4];
            *(float4*)(a)     = *(const float4*)(&As[kk][ty * 8]);
            *(float4*)(a + 4) = *(const float4*)(&As[kk][ty * 8 + 4]);
            *(float4*)(b)     = *(const float4*)(&Bs[kk][tx * 4]);
#pragma unroll
            for (int m = 0; m < 8; m++)
#pragma unroll
                for (int n = 0; n < 4; n++)
                    acc[m][n] = fmaf(a[m], b[n], acc[m][n]);
        }
        __syncthreads();
    }

    float4 bv = *(const float4*)(bias + bn + tx * 4);
#pragma unroll
    for (int m = 0; m < 8; m++) {
        int row = bm + ty * 8 + m;
        float4 ov;
        ov.x = acc[m][0] + bv.x;
        ov.y = acc[m][1] + bv.y;
        ov.z = acc[m][2] + bv.z;
        ov.w = acc[m][3] + bv.w;
        *(float4*)(C + (size_t)row * N + bn + tx * 4) = ov;
    }
}

// ---------------- neighbor compaction: 1 block (8 warps) per ligand, 2-pass ----------------
__global__ __launch_bounds__(256) void compact_kernel(
    const float* __restrict__ x_lig, const float* __restrict__ x_pok)
{
    const int i    = blockIdx.x;
    const int tid  = threadIdx.x;
    const int lane = tid & 31;
    const int w    = tid >> 5;          // 8 warps
    const int SPAN = N_POK / 8;         // 1024 pockets per warp

    __shared__ int sCnt[8], sOff[8];

    const float xi0 = x_lig[i * 3 + 0];
    const float xi1 = x_lig[i * 3 + 1];
    const float xi2 = x_lig[i * 3 + 2];
    const int j0 = w * SPAN;

    // pass 1: count
    int cnt = 0;
    for (int c = 0; c < SPAN; c += 32) {
        int j = j0 + c + lane;
        float r0 = x_pok[j * 3 + 0] - xi0;
        float r1 = x_pok[j * 3 + 1] - xi1;
        float r2 = x_pok[j * 3 + 2] - xi2;
        float d = sqrtf(r0 * r0 + r1 * r1 + r2 * r2);
        cnt += __popc(__ballot_sync(0xffffffffu, d < 10.0f));
    }
    if (lane == 0) sCnt[w] = cnt;
    __syncthreads();
    if (tid == 0) {
        int a = 0;
#pragma unroll
        for (int k = 0; k < 8; k++) { sOff[k] = a; a += sCnt[k]; }
        g_cnt[i] = a;
    }
    __syncthreads();

    // pass 2: write compacted indices + geometry
    int base = sOff[w];
    int*    row = g_nbr + (size_t)i * N_POK;
    float4* geo = g_geo + (size_t)i * N_POK;
    for (int c = 0; c < SPAN; c += 32) {
        int j = j0 + c + lane;
        float r0 = x_pok[j * 3 + 0] - xi0;
        float r1 = x_pok[j * 3 + 1] - xi1;
        float r2 = x_pok[j * 3 + 2] - xi2;
        float d = sqrtf(r0 * r0 + r1 * r1 + r2 * r2);
        bool m = d < 10.0f;
        unsigned bal = __ballot_sync(0xffffffffu, m);
        if (m) {
            int p = base + __popc(bal & ((1u << lane) - 1u));
            row[p] = j;
            float inv = __fdividef(1.f, d + 1e-8f);
            geo[p] = make_float4(r0 * inv, r1 * inv, r2 * inv, d);
        }
        base += __popc(bal);
    }
}

// ---------------- fused attention + epilogue: 1 block (256 thr) per ligand ----------------
__global__ __launch_bounds__(256) void attn_kernel(
    const float* __restrict__ h_lig, const float* __restrict__ x_lig,
    const float* __restrict__ ow,  const float* __restrict__ ob,
    const float* __restrict__ c1w, const float* __restrict__ c1b,
    const float* __restrict__ c2w, const float* __restrict__ c2b,
    float* __restrict__ out)
{
    const int i    = blockIdx.x;
    const int tid  = threadIdx.x;      // 256
    const int lane = tid & 31;
    const int wrp  = tid >> 5;         // 8 warps
    const int hh   = tid >> 6;         // head of this output element

    __shared__ float sQ[D];
    __shared__ float sS[32 * 4];       // tile scores [j][h]
    __shared__ float sP[32 * 4];       // tile probs  [j][h]
    __shared__ float sU[32 * 3];       // unit rel-pos
    __shared__ float sD[32];           // distances
    __shared__ int   sJ[32];
    __shared__ float sM[4], sL[4], sAl[4];
    __shared__ float sC[12];           // coord numerators [h][dim]
    __shared__ float sHa[D];
    __shared__ float sRed[8];

    sQ[tid] = g_Q[(size_t)i * D + tid];
    if (tid < 4)  { sM[tid] = -INFINITY; sL[tid] = 0.f; }
    if (tid < 12) sC[tid] = 0.f;

    float o = 0.f;   // this thread's output element (dim tid)
    const int cnt = g_cnt[i];
    __syncthreads();

    // per-lane Q registers, two 32-chunks per head
    const float q00 = sQ[lane],       q01 = sQ[lane + 32];
    const float q10 = sQ[64 + lane],  q11 = sQ[96 + lane];
    const float q20 = sQ[128 + lane], q21 = sQ[160 + lane];
    const float q30 = sQ[192 + lane], q31 = sQ[224 + lane];

    for (int t0 = 0; t0 < cnt; t0 += 32) {
        const int tn = min(32, cnt - t0);
        if (tid < tn) {
            sJ[tid] = g_nbr[(size_t)i * N_POK + t0 + tid];
            float4 g = g_geo[(size_t)i * N_POK + t0 + tid];
            sU[tid * 3 + 0] = g.x;
            sU[tid * 3 + 1] = g.y;
            sU[tid * 3 + 2] = g.z;
            sD[tid] = g.w;
        }
        __syncthreads();

        // ---- phase A: QK dot + table edge bias; warp w handles jj = w, w+8, ... ----
        for (int jj = wrp; jj < tn; jj += 8) {
            const int jn = sJ[jj];
            const float* Kr = g_K + (size_t)jn * D;
            float s0 = q00 * Kr[lane]       + q01 * Kr[lane + 32];
            float s1 = q10 * Kr[64 + lane]  + q11 * Kr[96 + lane];
            float s2 = q20 * Kr[128 + lane] + q21 * Kr[160 + lane];
            float s3 = q30 * Kr[192 + lane] + q31 * Kr[224 + lane];

#pragma unroll
            for (int off = 16; off; off >>= 1) {
                s0 += __shfl_xor_sync(0xffffffffu, s0, off);
                s1 += __shfl_xor_sync(0xffffffffu, s1, off);
                s2 += __shfl_xor_sync(0xffffffffu, s2, off);
                s3 += __shfl_xor_sync(0xffffffffu, s3, off);
            }
            if (lane == 0) {
                float t = sD[jj] * TAB_SCALE;
                int it = min((int)t, NTAB - 1);
                float fr = t - (float)it;
                float4 ea = g_tab[it];
                float4 eb = g_tab[it + 1];
                sS[jj * 4 + 0] = fmaf(s0, 0.125f, fmaf(fr, eb.x - ea.x, ea.x));
                sS[jj * 4 + 1] = fmaf(s1, 0.125f, fmaf(fr, eb.y - ea.y, ea.y));
                sS[jj * 4 + 2] = fmaf(s2, 0.125f, fmaf(fr, eb.z - ea.z, ea.z));
                sS[jj * 4 + 3] = fmaf(s3, 0.125f, fmaf(fr, eb.w - ea.w, ea.w));
            }
        }
        __syncthreads();

        // ---- phase B: online softmax bookkeeping, one warp per head ----
        if (wrp < 4) {
            const int h2 = wrp;
            float v = (lane < tn) ? sS[lane * 4 + h2] : -INFINITY;
            float mx = v;
#pragma unroll
            for (int off = 16; off; off >>= 1)
                mx = fmaxf(mx, __shfl_xor_sync(0xffffffffu, mx, off));
            float mold = sM[h2];
            float mnew = fmaxf(mold, mx);
            float p = (lane < tn) ? __expf(v - mnew) : 0.f;
            sP[lane * 4 + h2] = p;
            float sum = p;
#pragma unroll
            for (int off = 16; off; off >>= 1)
                sum += __shfl_xor_sync(0xffffffffu, sum, off);
            if (lane == 0) {
                float al = __expf(mold - mnew);   // 0 on first tile
                sAl[h2] = al;
                sL[h2]  = sL[h2] * al + sum;
                sM[h2]  = mnew;
            }
        }
        __syncthreads();

        // ---- phase C: accumulate V (all 256 threads) + coord numerators ----
        {
            float al = sAl[hh];
            o *= al;
            int jj = 0;
            for (; jj + 4 <= tn; jj += 4) {
                int j0 = sJ[jj], j1 = sJ[jj + 1], j2 = sJ[jj + 2], j3 = sJ[jj + 3];
                float p0 = sP[(jj + 0) * 4 + hh];
                float p1 = sP[(jj + 1) * 4 + hh];
                float p2 = sP[(jj + 2) * 4 + hh];
                float p3 = sP[(jj + 3) * 4 + hh];
                float v0 = g_V[(size_t)j0 * D + tid];
                float v1 = g_V[(size_t)j1 * D + tid];
                float v2 = g_V[(size_t)j2 * D + tid];
                float v3 = g_V[(size_t)j3 * D + tid];
                o = fmaf(p0, v0, o);
                o = fmaf(p1, v1, o);
                o = fmaf(p2, v2, o);
                o = fmaf(p3, v3, o);
            }
            for (; jj < tn; jj++)
                o = fmaf(sP[jj * 4 + hh], g_V[(size_t)sJ[jj] * D + tid], o);
        }
        if (tid < 12) {
            int h2 = tid / 3, dd = tid - h2 * 3;
            float c = sC[tid] * sAl[h2];
            for (int jj = 0; jj < tn; jj++)
                c = fmaf(sP[jj * 4 + h2], sU[jj * 3 + dd], c);
            sC[tid] = c;
        }
        __syncthreads();
    }

    // ---- finalize: normalize, epilogue matvecs, coord update ----
    float l  = sL[hh];
    float ha = (l > 0.f) ? o * __fdividef(1.f, l) : 0.f;   // nan_to_num for empty rows
    sHa[tid] = ha;
    __syncthreads();

    // h_out = h_lig + h_attended @ ow + ob
    float acc = ob[tid];
#pragma unroll 8
    for (int k = 0; k < D; k++)
        acc = fmaf(sHa[k], ow[(size_t)k * D + tid], acc);
    out[(size_t)i * D + tid] = h_lig[(size_t)i * D + tid] + acc;

    // coord_scale = silu(h_attended @ c1w + c1b) @ c2w + c2b
    float acc2 = c1b[tid];
#pragma unroll 8
    for (int k = 0; k < D; k++)
        acc2 = fmaf(sHa[k], c1w[(size_t)k * D + tid], acc2);
    float z = __fdividef(acc2, 1.f + __expf(-acc2)) * c2w[tid];
#pragma unroll
    for (int off = 16; off; off >>= 1)
        z += __shfl_xor_sync(0xffffffffu, z, off);
    if (lane == 0) sRed[wrp] = z;
    __syncthreads();

    if (tid == 0) {
        float sc = c2b[0];
#pragma unroll
        for (int r = 0; r < 8; r++) sc += sRed[r];
        float* ox = out + (size_t)N_LIG * D;
#pragma unroll
        for (int dd = 0; dd < 3; dd++) {
            float cm = 0.f;
#pragma unroll
            for (int h2 = 0; h2 < 4; h2++) {
                float lh = sL[h2];
                if (lh > 0.f) cm += __fdividef(sC[h2 * 3 + dd], lh);
            }
            cm *= 0.25f;   // mean over heads
            ox[i * 3 + dd] = x_lig[i * 3 + dd] + sc * cm;
        }
    }
}

// ---------------- launch ----------------
extern "C" void kernel_launch(void* const* d_in, const int* in_sizes, int n_in,
                              void* d_out, int out_size)
{
    const float* h_lig = (const float*)d_in[0];
    const float* x_lig = (const float*)d_in[1];
    const float* h_ato = (const float*)d_in[2];
    const float* x_pok = (const float*)d_in[3];
    const float* qw  = (const float*)d_in[4];
    const float* qb  = (const float*)d_in[5];
    const float* kw  = (const float*)d_in[6];
    const float* kb  = (const float*)d_in[7];
    const float* vw  = (const float*)d_in[8];
    const float* vb  = (const float*)d_in[9];
    const float* ow  = (const float*)d_in[10];
    const float* ob  = (const float*)d_in[11];
    const float* e1w = (const float*)d_in[12];
    const float* e1b = (const float*)d_in[13];
    const float* e2w = (const float*)d_in[14];
    const float* e2b = (const float*)d_in[15];
    const float* c1w = (const float*)d_in[16];
    const float* c1b = (const float*)d_in[17];
    const float* c2w = (const float*)d_in[18];
    const float* c2b = (const float*)d_in[19];
    float* out = (float*)d_out;

    void *pQ, *pK, *pV;
    cudaGetSymbolAddress(&pQ, g_Q);
    cudaGetSymbolAddress(&pK, g_K);
    cudaGetSymbolAddress(&pV, g_V);

    // edge-attr lookup table (8193 entries, one warp each)
    edge_tab_kernel<<<(NTAB + 8) / 8, 256>>>(e1w, e1b, e2w, e2b);

    // neighbor compaction
    compact_kernel<<<N_LIG, 256>>>(x_lig, x_pok);

    // projections
    gemm_bias_kernel<<<dim3(D / BN, N_LIG / BM), 256>>>(h_lig, qw, qb, (float*)pQ, N_LIG, D, D);
    gemm_bias_kernel<<<dim3(D / BN, N_POK / BM), 256>>>(h_ato, kw, kb, (float*)pK, N_POK, D, ADIM);
    gemm_bias_kernel<<<dim3(D / BN, N_POK / BM), 256>>>(h_ato, vw, vb, (float*)pV, N_POK, D, ADIM);

    // fused attention + epilogue
    attn_kernel<<<N_LIG, 256>>>(h_lig, x_lig,
                                ow, ob, c1w, c1b, c2w, c2b, out);
}

// round 15
// speedup vs baseline: 1.4327x; 1.0005x over previous
#include <cuda_runtime.h>
#include <math.h>

#define N_LIG 1024
#define N_POK 8192
#define D     256
#define ADIM  512
#define NH    4
#define HD    64

#define NTAB      8192
#define TAB_SCALE (NTAB / 10.0f)     // d in [0,10) -> index
#define TAB_INV   (10.0f / NTAB)
#define TAB_BLOCKS ((NTAB + 1 + 255) / 256)   // 33

// ---------------- device scratch (no allocations allowed) ----------------
__device__ float  g_K[N_POK * D];
__device__ float  g_V[N_POK * D];
__device__ int    g_nbr[(size_t)N_LIG * N_POK];
__device__ float4 g_geo[(size_t)N_LIG * N_POK];   // (ux, uy, uz, d) per compacted pair
__device__ int    g_cnt[N_LIG];
__device__ float4 g_tab[NTAB + 1];                // edge_attr(d) + e2b, per head

// ---------------- tiled FP32 GEMM: C[M,N] = A[M,K] @ W[K,N] + bias ----------------
#define BM 128
#define BN 64
#define BK 16

__global__ __launch_bounds__(256) void gemm_bias_kernel(
    const float* __restrict__ A, const float* __restrict__ W,
    const float* __restrict__ bias, float* __restrict__ C,
    int M, int N, int K)
{
    __shared__ float As[BK][BM + 4];
    __shared__ float Bs[BK][BN];

    const int tid = threadIdx.x;
    const int bm = blockIdx.y * BM;
    const int bn = blockIdx.x * BN;
    const int tx = tid & 15;        // 0..15 -> 4 output cols each
    const int ty = tid >> 4;        // 0..15 -> 8 output rows each

    float acc[8][4];
#pragma unroll
    for (int m = 0; m < 8; m++)
#pragma unroll
        for (int n = 0; n < 4; n++) acc[m][n] = 0.f;

    for (int k0 = 0; k0 < K; k0 += BK) {
#pragma unroll
        for (int ld = 0; ld < 2; ld++) {
            int f = tid * 2 + ld;
            int row = f >> 2;
            int c4 = (f & 3) * 4;
            float4 v = *(const float4*)(A + (size_t)(bm + row) * K + k0 + c4);
            As[c4 + 0][row] = v.x;
            As[c4 + 1][row] = v.y;
            As[c4 + 2][row] = v.z;
            As[c4 + 3][row] = v.w;
        }
        {
            int r = tid >> 4;
            int c4 = (tid & 15) * 4;
            *(float4*)(&Bs[r][c4]) = *(const float4*)(W + (size_t)(k0 + r) * N + bn + c4);
        }
        __syncthreads();

#pragma unroll
        for (int kk = 0; kk < BK; kk++) {
            float a[8], b[4];
            *(float4*)(a)     = *(const float4*)(&As[kk][ty * 8]);
            *(float4*)(a + 4) = *(const float4*)(&As[kk][ty * 8 + 4]);
            *(float4*)(b)     = *(const float4*)(&Bs[kk][tx * 4]);
#pragma unroll
            for (int m = 0; m < 8; m++)
#pragma unroll
                for (int n = 0; n < 4; n++)
                    acc[m][n] = fmaf(a[m], b[n], acc[m][n]);
        }
        __syncthreads();
    }

    float4 bv = *(const float4*)(bias + bn + tx * 4);
#pragma unroll
    for (int m = 0; m < 8; m++) {
        int row = bm + ty * 8 + m;
        float4 ov;
        ov.x = acc[m][0] + bv.x;
        ov.y = acc[m][1] + bv.y;
        ov.z = acc[m][2] + bv.z;
        ov.w = acc[m][3] + bv.w;
        *(float4*)(C + (size_t)row * N + bn + tx * 4) = ov;
    }
}

// ---------------- fused: neighbor compaction (blocks < N_LIG) + edge table (rest) ----------------
__global__ __launch_bounds__(256) void compact_tab_kernel(
    const float* __restrict__ x_lig, const float* __restrict__ x_pok,
    const float* __restrict__ e1w, const float* __restrict__ e1b,
    const float* __restrict__ e2w, const float* __restrict__ e2b)
{
    const int tid  = threadIdx.x;

    if (blockIdx.x >= N_LIG) {
        // -------- edge-attr table: one thread per entry, serial 256-hidden eval --------
        const int entry = (blockIdx.x - N_LIG) * 256 + tid;
        if (entry <= NTAB) {
            const float d = entry * TAB_INV;
            float a0 = 0.f, a1 = 0.f, a2 = 0.f, a3 = 0.f;
            for (int k = 0; k < D; k++) {
                float t  = fmaf(d, e1w[k], e1b[k]);
                float sv = __fdividef(t, 1.f + __expf(-t));
                float4 w4 = *(const float4*)(&e2w[k * 4]);
                a0 = fmaf(sv, w4.x, a0);
                a1 = fmaf(sv, w4.y, a1);
                a2 = fmaf(sv, w4.z, a2);
                a3 = fmaf(sv, w4.w, a3);
            }
            g_tab[entry] = make_float4(a0 + e2b[0], a1 + e2b[1], a2 + e2b[2], a3 + e2b[3]);
        }
        return;
    }

    // -------- compaction: 1 block (8 warps) per ligand, 2-pass --------
    const int i    = blockIdx.x;
    const int lane = tid & 31;
    const int w    = tid >> 5;          // 8 warps
    const int SPAN = N_POK / 8;         // 1024 pockets per warp

    __shared__ int sCnt[8], sOff[8];

    const float xi0 = x_lig[i * 3 + 0];
    const float xi1 = x_lig[i * 3 + 1];
    const float xi2 = x_lig[i * 3 + 2];
    const int j0 = w * SPAN;

    // pass 1: count
    int cnt = 0;
    for (int c = 0; c < SPAN; c += 32) {
        int j = j0 + c + lane;
        float r0 = x_pok[j * 3 + 0] - xi0;
        float r1 = x_pok[j * 3 + 1] - xi1;
        float r2 = x_pok[j * 3 + 2] - xi2;
        float d = sqrtf(r0 * r0 + r1 * r1 + r2 * r2);
        cnt += __popc(__ballot_sync(0xffffffffu, d < 10.0f));
    }
    if (lane == 0) sCnt[w] = cnt;
    __syncthreads();
    if (tid == 0) {
        int a = 0;
#pragma unroll
        for (int k = 0; k < 8; k++) { sOff[k] = a; a += sCnt[k]; }
        g_cnt[i] = a;
    }
    __syncthreads();

    // pass 2: write compacted indices + geometry
    int base = sOff[w];
    int*    row = g_nbr + (size_t)i * N_POK;
    float4* geo = g_geo + (size_t)i * N_POK;
    for (int c = 0; c < SPAN; c += 32) {
        int j = j0 + c + lane;
        float r0 = x_pok[j * 3 + 0] - xi0;
        float r1 = x_pok[j * 3 + 1] - xi1;
        float r2 = x_pok[j * 3 + 2] - xi2;
        float d = sqrtf(r0 * r0 + r1 * r1 + r2 * r2);
        bool m = d < 10.0f;
        unsigned bal = __ballot_sync(0xffffffffu, m);
        if (m) {
            int p = base + __popc(bal & ((1u << lane) - 1u));
            row[p] = j;
            float inv = __fdividef(1.f, d + 1e-8f);
            geo[p] = make_float4(r0 * inv, r1 * inv, r2 * inv, d);
        }
        base += __popc(bal);
    }
}

// ---------------- fused attention + Q projection + epilogue: 1 block per ligand ----------------
__global__ __launch_bounds__(256) void attn_kernel(
    const float* __restrict__ h_lig, const float* __restrict__ x_lig,
    const float* __restrict__ qw,  const float* __restrict__ qb,
    const float* __restrict__ ow,  const float* __restrict__ ob,
    const float* __restrict__ c1w, const float* __restrict__ c1b,
    const float* __restrict__ c2w, const float* __restrict__ c2b,
    float* __restrict__ out)
{
    const int i    = blockIdx.x;
    const int tid  = threadIdx.x;      // 256
    const int lane = tid & 31;
    const int wrp  = tid >> 5;         // 8 warps
    const int hh   = tid >> 6;         // head of this output element

    __shared__ float sQ[D];
    __shared__ float sS[32 * 4];       // tile scores [j][h]
    __shared__ float sP[32 * 4];       // tile probs  [j][h]
    __shared__ float sU[32 * 3];       // unit rel-pos
    __shared__ float sD[32];           // distances
    __shared__ int   sJ[32];
    __shared__ float sM[4], sL[4], sAl[4];
    __shared__ float sC[12];           // coord numerators [h][dim]
    __shared__ float sHa[D];           // (prologue: h_lig row; finale: h_attended)
    __shared__ float sRed[8];

    // ---- prologue: Q projection for this ligand (Q = h @ qw + qb) ----
    sHa[tid] = h_lig[(size_t)i * D + tid];
    if (tid < 4)  { sM[tid] = -INFINITY; sL[tid] = 0.f; }
    if (tid < 12) sC[tid] = 0.f;
    __syncthreads();

    {
        float qacc = qb[tid];
#pragma unroll 8
        for (int k = 0; k < D; k++)
            qacc = fmaf(sHa[k], qw[(size_t)k * D + tid], qacc);
        sQ[tid] = qacc;
    }

    float o = 0.f;   // this thread's output element (dim tid)
    const int cnt = g_cnt[i];
    __syncthreads();

    // per-lane Q registers, two 32-chunks per head
    const float q00 = sQ[lane],       q01 = sQ[lane + 32];
    const float q10 = sQ[64 + lane],  q11 = sQ[96 + lane];
    const float q20 = sQ[128 + lane], q21 = sQ[160 + lane];
    const float q30 = sQ[192 + lane], q31 = sQ[224 + lane];

    for (int t0 = 0; t0 < cnt; t0 += 32) {
        const int tn = min(32, cnt - t0);
        if (tid < tn) {
            sJ[tid] = g_nbr[(size_t)i * N_POK + t0 + tid];
            float4 g = g_geo[(size_t)i * N_POK + t0 + tid];
            sU[tid * 3 + 0] = g.x;
            sU[tid * 3 + 1] = g.y;
            sU[tid * 3 + 2] = g.z;
            sD[tid] = g.w;
        }
        __syncthreads();

        // ---- phase A: QK dot + table edge bias; warp w handles jj = w, w+8, ... ----
        for (int jj = wrp; jj < tn; jj += 8) {
            const int jn = sJ[jj];
            const float* Kr = g_K + (size_t)jn * D;
            float s0 = q00 * Kr[lane]       + q01 * Kr[lane + 32];
            float s1 = q10 * Kr[64 + lane]  + q11 * Kr[96 + lane];
            float s2 = q20 * Kr[128 + lane] + q21 * Kr[160 + lane];
            float s3 = q30 * Kr[192 + lane] + q31 * Kr[224 + lane];

#pragma unroll
            for (int off = 16; off; off >>= 1) {
                s0 += __shfl_xor_sync(0xffffffffu, s0, off);
                s1 += __shfl_xor_sync(0xffffffffu, s1, off);
                s2 += __shfl_xor_sync(0xffffffffu, s2, off);
                s3 += __shfl_xor_sync(0xffffffffu, s3, off);
            }
            if (lane == 0) {
                float t = sD[jj] * TAB_SCALE;
                int it = min((int)t, NTAB - 1);
                float fr = t - (float)it;
                float4 ea = g_tab[it];
                float4 eb = g_tab[it + 1];
                sS[jj * 4 + 0] = fmaf(s0, 0.125f, fmaf(fr, eb.x - ea.x, ea.x));
                sS[jj * 4 + 1] = fmaf(s1, 0.125f, fmaf(fr, eb.y - ea.y, ea.y));
                sS[jj * 4 + 2] = fmaf(s2, 0.125f, fmaf(fr, eb.z - ea.z, ea.z));
                sS[jj * 4 + 3] = fmaf(s3, 0.125f, fmaf(fr, eb.w - ea.w, ea.w));
            }
        }
        __syncthreads();

        // ---- phase B: online softmax bookkeeping, one warp per head ----
        if (wrp < 4) {
            const int h2 = wrp;
            float v = (lane < tn) ? sS[lane * 4 + h2] : -INFINITY;
            float mx = v;
#pragma unroll
            for (int off = 16; off; off >>= 1)
                mx = fmaxf(mx, __shfl_xor_sync(0xffffffffu, mx, off));
            float mold = sM[h2];
            float mnew = fmaxf(mold, mx);
            float p = (lane < tn) ? __expf(v - mnew) : 0.f;
            sP[lane * 4 + h2] = p;
            float sum = p;
#pragma unroll
            for (int off = 16; off; off >>= 1)
                sum += __shfl_xor_sync(0xffffffffu, sum, off);
            if (lane == 0) {
                float al = __expf(mold - mnew);   // 0 on first tile
                sAl[h2] = al;
                sL[h2]  = sL[h2] * al + sum;
                sM[h2]  = mnew;
            }
        }
        __syncthreads();

        // ---- phase C: accumulate V (all 256 threads) + coord numerators ----
        {
            float al = sAl[hh];
            o *= al;
            int jj = 0;
            for (; jj + 4 <= tn; jj += 4) {
                int j0 = sJ[jj], j1 = sJ[jj + 1], j2 = sJ[jj + 2], j3 = sJ[jj + 3];
                float p0 = sP[(jj + 0) * 4 + hh];
                float p1 = sP[(jj + 1) * 4 + hh];
                float p2 = sP[(jj + 2) * 4 + hh];
                float p3 = sP[(jj + 3) * 4 + hh];
                float v0 = g_V[(size_t)j0 * D + tid];
                float v1 = g_V[(size_t)j1 * D + tid];
                float v2 = g_V[(size_t)j2 * D + tid];
                float v3 = g_V[(size_t)j3 * D + tid];
                o = fmaf(p0, v0, o);
                o = fmaf(p1, v1, o);
                o = fmaf(p2, v2, o);
                o = fmaf(p3, v3, o);
            }
            for (; jj < tn; jj++)
                o = fmaf(sP[jj * 4 + hh], g_V[(size_t)sJ[jj] * D + tid], o);
        }
        if (tid < 12) {
            int h2 = tid / 3, dd = tid - h2 * 3;
            float c = sC[tid] * sAl[h2];
            for (int jj = 0; jj < tn; jj++)
                c = fmaf(sP[jj * 4 + h2], sU[jj * 3 + dd], c);
            sC[tid] = c;
        }
        __syncthreads();
    }

    // ---- finalize: normalize, epilogue matvecs, coord update ----
    float l  = sL[hh];
    float ha = (l > 0.f) ? o * __fdividef(1.f, l) : 0.f;   // nan_to_num for empty rows
    __syncthreads();          // all reads of sHa (h_lig) done; safe to overwrite
    sHa[tid] = ha;
    __syncthreads();

    // h_out = h_lig + h_attended @ ow + ob
    float acc = ob[tid];
#pragma unroll 8
    for (int k = 0; k < D; k++)
        acc = fmaf(sHa[k], ow[(size_t)k * D + tid], acc);
    out[(size_t)i * D + tid] = h_lig[(size_t)i * D + tid] + acc;

    // coord_scale = silu(h_attended @ c1w + c1b) @ c2w + c2b
    float acc2 = c1b[tid];
#pragma unroll 8
    for (int k = 0; k < D; k++)
        acc2 = fmaf(sHa[k], c1w[(size_t)k * D + tid], acc2);
    float z = __fdividef(acc2, 1.f + __expf(-acc2)) * c2w[tid];
#pragma unroll
    for (int off = 16; off; off >>= 1)
        z += __shfl_xor_sync(0xffffffffu, z, off);
    if (lane == 0) sRed[wrp] = z;
    __syncthreads();

    if (tid == 0) {
        float sc = c2b[0];
#pragma unroll
        for (int r = 0; r < 8; r++) sc += sRed[r];
        float* ox = out + (size_t)N_LIG * D;
#pragma unroll
        for (int dd = 0; dd < 3; dd++) {
            float cm = 0.f;
#pragma unroll
            for (int h2 = 0; h2 < 4; h2++) {
                float lh = sL[h2];
                if (lh > 0.f) cm += __fdividef(sC[h2 * 3 + dd], lh);
            }
            cm *= 0.25f;   // mean over heads
            ox[i * 3 + dd] = x_lig[i * 3 + dd] + sc * cm;
        }
    }
}

// ---------------- launch ----------------
extern "C" void kernel_launch(void* const* d_in, const int* in_sizes, int n_in,
                              void* d_out, int out_size)
{
    const float* h_lig = (const float*)d_in[0];
    const float* x_lig = (const float*)d_in[1];
    const float* h_ato = (const float*)d_in[2];
    const float* x_pok = (const float*)d_in[3];
    const float* qw  = (const float*)d_in[4];
    const float* qb  = (const float*)d_in[5];
    const float* kw  = (const float*)d_in[6];
    const float* kb  = (const float*)d_in[7];
    const float* vw  = (const float*)d_in[8];
    const float* vb  = (const float*)d_in[9];
    const float* ow  = (const float*)d_in[10];
    const float* ob  = (const float*)d_in[11];
    const float* e1w = (const float*)d_in[12];
    const float* e1b = (const float*)d_in[13];
    const float* e2w = (const float*)d_in[14];
    const float* e2b = (const float*)d_in[15];
    const float* c1w = (const float*)d_in[16];
    const float* c1b = (const float*)d_in[17];
    const float* c2w = (const float*)d_in[18];
    const float* c2b = (const float*)d_in[19];
    float* out = (float*)d_out;

    void *pK, *pV;
    cudaGetSymbolAddress(&pK, g_K);
    cudaGetSymbolAddress(&pV, g_V);

    // launch 1: fused compaction + edge-attr table
    compact_tab_kernel<<<N_LIG + TAB_BLOCKS, 256>>>(x_lig, x_pok, e1w, e1b, e2w, e2b);

    // launches 2-3: K / V projections
    gemm_bias_kernel<<<dim3(D / BN, N_POK / BM), 256>>>(h_ato, kw, kb, (float*)pK, N_POK, D, ADIM);
    gemm_bias_kernel<<<dim3(D / BN, N_POK / BM), 256>>>(h_ato, vw, vb, (float*)pV, N_POK, D, ADIM);

    // launch 4: fused Q projection + attention + epilogue  (profiler window target)
    attn_kernel<<<N_LIG, 256>>>(h_lig, x_lig, qw, qb,
                                ow, ob, c1w, c1b, c2w, c2b, out);
}